// round 13
// baseline (speedup 1.0000x reference)
#include <cuda_runtime.h>
#include <cuda_fp16.h>
#include <cstdint>

// InstanceConv via warp-level mma.sync GEMM (compute_103-safe).
// Round 13: f16-ACCUMULATE mma (2x rate vs f32-accum ceiling) with fp32
// promotion in CUDA cores every 2 C-chained mma (k=32). R10 frame:
// 2-row x 128-px tiles, 16 warps, bulk-copy staging, work stealing.
// B=8, C=64, OC=64, H=W=128, K=3, pad=1.

#define BATCH 8
#define CH 64
#define OCN 64
#define HDIM 128
#define WDIM 128
#define NTILES 512                   // 2-row x 128-px tiles
#define GRID_MAIN 152
#define NTHREADS 512
#define OUT_MASK_OFF (BATCH * OCN * HDIM * WDIM)   // 8388608

// ---- smem layout (bytes) ----
#define OFF_W 0
#define W_BYTES (9 * 8192)               // 73728: [tap] 64(c)x64(o) f16, swizzled
#define SLOT_B 16640                     // one X row slot: [xi:130][c:64] f16 swz
#define OFF_X (OFF_W + W_BYTES)          // 73728: 2 buffers x 4 slots
#define OFF_M (OFF_X + 8 * SLOT_B)       // 206848: 2 x mask [4][132] f32
#define MASK_BUF 2112
#define OFF_B (OFF_M + 2 * MASK_BUF)     // 211072: bias
#define OFF_CTRL (OFF_B + 256)           // 211328: [0]=next tile u32; +16/+24 mbars
#define SMEM_TOTAL (OFF_CTRL + 32)       // 211360

__device__ uint32_t g_xt[BATCH * HDIM * WDIM * 32];  // [b][y][xb:16][1KB swizzled]
__device__ uint4 g_wimg[W_BYTES / 16];
__device__ int g_ctr;

__device__ __forceinline__ uint32_t smem_u32(const void* p) {
    uint32_t a;
    asm("{ .reg .u64 t; cvta.to.shared.u64 t, %1; cvt.u32.u64 %0, t; }" : "=r"(a) : "l"(p));
    return a;
}
__device__ __forceinline__ void ldsm_x4(uint32_t addr, uint32_t* r) {
    asm volatile("ldmatrix.sync.aligned.m8n8.x4.shared.b16 {%0,%1,%2,%3}, [%4];"
                 : "=r"(r[0]), "=r"(r[1]), "=r"(r[2]), "=r"(r[3]) : "r"(addr));
}
__device__ __forceinline__ void ldsm_x4t(uint32_t addr, uint32_t* r) {
    asm volatile("ldmatrix.sync.aligned.m8n8.x4.trans.shared.b16 {%0,%1,%2,%3}, [%4];"
                 : "=r"(r[0]), "=r"(r[1]), "=r"(r[2]), "=r"(r[3]) : "r"(addr));
}
// f16-accumulate mma: D(f16x2 x2) = A*B + C(f16x2 x2)
__device__ __forceinline__ void mma_f16h(uint32_t* d, const uint32_t* a,
                                         uint32_t b0, uint32_t b1,
                                         uint32_t c0, uint32_t c1) {
    asm volatile("mma.sync.aligned.m16n8k16.row.col.f16.f16.f16.f16 "
                 "{%0,%1}, {%2,%3,%4,%5}, {%6,%7}, {%8,%9};"
                 : "=r"(d[0]), "=r"(d[1])
                 : "r"(a[0]), "r"(a[1]), "r"(a[2]), "r"(a[3]),
                   "r"(b0), "r"(b1), "r"(c0), "r"(c1));
}
__device__ __forceinline__ void promote(float* D, uint32_t t0, uint32_t t1) {
    float2 f0 = __half22float2(*reinterpret_cast<__half2*>(&t0));
    float2 f1 = __half22float2(*reinterpret_cast<__half2*>(&t1));
    D[0] += f0.x; D[1] += f0.y; D[2] += f1.x; D[3] += f1.y;
}
__device__ __forceinline__ void cpasync16(uint32_t d, const void* s) {
    asm volatile("cp.async.ca.shared.global [%0], [%1], 16;"
                 :: "r"(d), "l"(s) : "memory");
}
#define MBARRIER_INIT(a, n) \
    asm volatile("mbarrier.init.shared.b64 [%0], %1;" :: "r"(a), "r"((uint32_t)(n)) : "memory")
#define MBARRIER_EXPECT_TX(a, tx) \
    asm volatile("mbarrier.arrive.expect_tx.shared.b64 _, [%0], %1;" \
                 :: "r"(a), "r"((uint32_t)(tx)) : "memory")
#define MBARRIER_WAIT_PARITY(a, par) do {                                         \
    uint32_t _m = (a); uint32_t _p = (uint32_t)(par); uint32_t _d;                \
    asm volatile("{\n\t.reg .pred p;\n\t"                                         \
        "mbarrier.try_wait.parity.acquire.cta.shared::cta.b64 p, [%1], %2;\n\t"   \
        "selp.b32 %0, 1, 0, p;\n\t}" : "=r"(_d) : "r"(_m), "r"(_p) : "memory");   \
    if (!_d) {                                                                    \
        asm volatile("{\n\t.reg .pred P1;\n\t"                                    \
            "WL_%=:\n\t"                                                          \
            "mbarrier.try_wait.parity.acquire.cta.shared::cta.b64 P1, [%0], %1, 0x989680;\n\t" \
            "@P1 bra.uni WD_%=;\n\tbra.uni WL_%=;\n\tWD_%=:\n\t}"                 \
            :: "r"(_m), "r"(_p) : "memory");                                      \
    }                                                                             \
} while (0)
#define FENCE_ASYNC() asm volatile("fence.proxy.async.shared::cta;" ::: "memory")
__device__ __forceinline__ void bulk_cp(uint32_t dst, const void* src, uint32_t bytes,
                                        uint32_t mbar) {
    asm volatile("cp.async.bulk.shared::cta.global.mbarrier::complete_tx::bytes "
                 "[%0], [%1], %2, [%3];"
                 :: "r"(dst), "l"(src), "r"(bytes), "r"(mbar) : "memory");
}

// ---------------- prep kernel ----------------
__global__ void prep(const float* __restrict__ inp, const float* __restrict__ conv) {
    const int tid = threadIdx.x;
    if (blockIdx.x >= 2048) {
        if (blockIdx.x == 2048 && tid == 0) g_ctr = GRID_MAIN;
        int i = (blockIdx.x - 2048) * 256 + tid;
        if (i < 9 * 64 * 64) {
            int o = i & 63, c = (i >> 6) & 63, tap = i >> 12;
            __half h = __float2half(conv[(o * 64 + c) * 9 + tap]);
            unsigned short* img = (unsigned short*)g_wimg;
            uint32_t byte = (uint32_t)(c * 128 + ((((o >> 3) ^ (c & 7))) << 4) + (o & 7) * 2);
            img[(tap * 8192 + byte) >> 1] = __half_as_ushort(h);
        }
        return;
    }
    __shared__ float tile[64][65];
    const int blk = blockIdx.x;
    const int half = blk & 1, y = (blk >> 1) & 127, b = blk >> 8;
    const int x0 = half * 64;
    #pragma unroll
    for (int i = 0; i < 16; ++i) {
        int idx = i * 256 + tid;
        int c = idx >> 6, x = idx & 63;
        tile[c][x] = inp[((b * CH + c) * HDIM + y) * WDIM + x0 + x];
    }
    __syncthreads();
    #pragma unroll
    for (int i = 0; i < 8; ++i) {
        int idx = i * 256 + tid;
        int x = (idx >> 5) + x0, cw = idx & 31;
        __half h0 = __float2half(tile[2 * (idx & 31)][idx >> 5]);
        __half h1 = __float2half(tile[2 * (idx & 31) + 1][idx >> 5]);
        uint32_t v = (uint32_t)__half_as_ushort(h0) | ((uint32_t)__half_as_ushort(h1) << 16);
        int u = cw >> 2;
        int dst = ((b * HDIM + y) << 12) + ((x >> 3) << 8) + ((x & 7) << 5)
                + (((u ^ (x & 7))) << 2) + (cw & 3);
        g_xt[dst] = v;
    }
}

// ---------------- main persistent kernel ----------------
__global__ __launch_bounds__(NTHREADS, 1)
void instconv_mma(const float* __restrict__ mask,
                  const float* __restrict__ bias,
                  float* __restrict__ out) {
    extern __shared__ char smem[];
    const uint32_t sb = smem_u32(smem);
    const int tid = threadIdx.x;
    const int wid = tid >> 5;
    const int lane = tid & 31;
    const int g = lane >> 2;
    const int t2 = (lane & 3) * 2;
    const int h = wid >> 3;           // oc half (0: oc<32, 1: oc>=32)
    const int p0 = (wid & 7) * 16;    // 16-px group
    const int lane15 = lane & 15;
    const int laneHi = lane >> 4;

    volatile int* sCtrl = (volatile int*)(smem + OFF_CTRL);
    const uint32_t mbarA[2] = { sb + OFF_CTRL + 16, sb + OFF_CTRL + 24 };

    // stage weights once (cp.async group)
    {
        const uint4* src = g_wimg;
        #pragma unroll 4
        for (int i = tid; i < W_BYTES / 16; i += NTHREADS)
            cpasync16(sb + OFF_W + i * 16, src + i);
        asm volatile("cp.async.commit_group;" ::: "memory");
    }
    if (tid < 64) ((float*)(smem + OFF_B))[tid] = bias[tid];
    if (tid == 0) { MBARRIER_INIT(mbarA[0], 1); MBARRIER_INIT(mbarA[1], 1); }
    const float* sB = (const float*)(smem + OFF_B);

    // W lane-constant swizzled col offsets for this oc half (2 x 16-oc blocks)
    const uint32_t wLane = sb + OFF_W + (uint32_t)(lane15 * 128);
    uint32_t wcs[2];
    #pragma unroll
    for (int j = 0; j < 2; ++j)
        wcs[j] = (uint32_t)(((((2 * h + j) * 2 + laneHi) ^ (lane & 7))) << 4);

    // ---- prologue: stage first tile ----
    int t = blockIdx.x;
    {
        const int b = t >> 6, y0 = (t & 63) * 2;
        if (tid == 0) {
            FENCE_ASYNC();
            MBARRIER_EXPECT_TX(mbarA[0], 4 * 16384);
            #pragma unroll
            for (int s = 0; s < 4; ++s) {
                int ys = y0 - 1 + s; ys = ys < 0 ? 0 : (ys > 127 ? 127 : ys);
                bulk_cp(sb + OFF_X + s * SLOT_B + 128,
                        g_xt + ((size_t)(b * HDIM + ys) << 12), 16384, mbarA[0]);
            }
        }
        float* sM0 = (float*)(smem + OFF_M);
        for (int i = tid; i < 528; i += NTHREADS) {
            int r = i / 132, xi = i - r * 132;
            int ys = y0 + r - 1, xs = xi - 1;
            float v = -1.0f;
            if ((unsigned)ys < (unsigned)HDIM && (unsigned)xs < (unsigned)WDIM)
                v = mask[(b * HDIM + ys) * WDIM + xs];
            sM0[i] = v;
        }
        if (tid == 0) sCtrl[0] = atomicAdd(&g_ctr, 1);
    }
    asm volatile("cp.async.wait_group 0;" ::: "memory");
    __syncthreads();   // W + mask + sCtrl visible

    int ph0 = 0, ph1 = 0;
    int buf = 0;

    for (;;) {
        const int b = t >> 6, y0 = (t & 63) * 2;

        // wait X staged for this tile
        if (buf == 0) { MBARRIER_WAIT_PARITY(mbarA[0], ph0); ph0 ^= 1; }
        else          { MBARRIER_WAIT_PARITY(mbarA[1], ph1); ph1 ^= 1; }

        const int tn = sCtrl[0];
        const bool have_next = tn < NTILES;
        __syncthreads();   // everyone has tn before thread0 overwrites sCtrl

        // prefetch next tile into other buffer
        const int bn = tn >> 6, yn0 = (tn & 63) * 2;
        if (tid == 0 && have_next) {
            FENCE_ASYNC();
            MBARRIER_EXPECT_TX(mbarA[buf ^ 1], 4 * 16384);
            #pragma unroll
            for (int s = 0; s < 4; ++s) {
                int ys = yn0 - 1 + s; ys = ys < 0 ? 0 : (ys > 127 ? 127 : ys);
                bulk_cp(sb + OFF_X + ((buf ^ 1) * 4 + s) * SLOT_B + 128,
                        g_xt + ((size_t)(bn * HDIM + ys) << 12), 16384, mbarA[buf ^ 1]);
            }
        }
        // mask prefetch for next tile into registers (STS at end of tile)
        float mr[2];
        #pragma unroll
        for (int j = 0; j < 2; ++j) {
            mr[j] = -1.0f;
            int i = tid + j * NTHREADS;
            if (have_next && i < 528) {
                int r = i / 132, xi = i - r * 132;
                int ys = yn0 + r - 1, xs = xi - 1;
                if ((unsigned)ys < (unsigned)HDIM && (unsigned)xs < (unsigned)WDIM)
                    mr[j] = mask[(bn * HDIM + ys) * WDIM + xs];
            }
        }
        if (tid == 0) sCtrl[0] = atomicAdd(&g_ctr, 1);

        const float* sMb = (const float*)(smem + OFF_M + buf * MASK_BUF);
        const float c00 = sMb[1 * 132 + 1 + p0 + g];
        const float c01 = sMb[1 * 132 + 1 + p0 + g + 8];
        const float c10 = sMb[2 * 132 + 1 + p0 + g];
        const float c11 = sMb[2 * 132 + 1 + p0 + g + 8];

        float D0[4][4], D1[4][4];
        #pragma unroll
        for (int nb = 0; nb < 4; ++nb)
            #pragma unroll
            for (int j = 0; j < 4; ++j) { D0[nb][j] = 0.0f; D1[nb][j] = 0.0f; }

        #pragma unroll
        for (int ky = 0; ky < 3; ++ky) {
            const uint32_t baseA0 = sb + OFF_X + (uint32_t)((buf * 4 + ky) * SLOT_B);
            const uint32_t baseA1 = baseA0 + SLOT_B;
            const float* mT0 = sMb + ky * 132;        // tap row for out-row 0
            const float* mT1 = sMb + (ky + 1) * 132;  // tap row for out-row 1

            #pragma unroll 1
            for (int kx = 0; kx < 3; ++kx) {
                const uint32_t mk00 = (mT0[p0 + g + kx]     == c00) ? 0xFFFFFFFFu : 0u;
                const uint32_t mk01 = (mT0[p0 + g + 8 + kx] == c01) ? 0xFFFFFFFFu : 0u;
                const uint32_t mk10 = (mT1[p0 + g + kx]     == c10) ? 0xFFFFFFFFu : 0u;
                const uint32_t mk11 = (mT1[p0 + g + 8 + kx] == c11) ? 0xFFFFFFFFu : 0u;

                const int xi = p0 + lane15 + kx;
                const uint32_t rowb = (uint32_t)(xi * 128);
                const int xorm = (lane15 + kx + 7) & 7;
                const uint32_t wTap = wLane + (uint32_t)((ky * 3 + kx) * 8192);

                #pragma unroll
                for (int kp = 0; kp < 2; ++kp) {
                    // load both k of this pair
                    uint32_t A0k[2][4], A1k[2][4], Wk[2][2][4];
                    #pragma unroll
                    for (int kk = 0; kk < 2; ++kk) {
                        const int k = kp * 2 + kk;
                        const uint32_t colA = (uint32_t)(((k * 2 + laneHi) ^ xorm) << 4);
                        ldsm_x4(baseA0 + rowb + colA, A0k[kk]);
                        ldsm_x4(baseA1 + rowb + colA, A1k[kk]);
                        A0k[kk][0] &= mk00; A0k[kk][2] &= mk00;
                        A0k[kk][1] &= mk01; A0k[kk][3] &= mk01;
                        A1k[kk][0] &= mk10; A1k[kk][2] &= mk10;
                        A1k[kk][1] &= mk11; A1k[kk][3] &= mk11;
                        const uint32_t wk = wTap + (uint32_t)(k * 2048);
                        ldsm_x4t(wk + wcs[0], Wk[kk][0]);
                        ldsm_x4t(wk + wcs[1], Wk[kk][1]);
                    }
                    // 8 chains: 2 C-chained f16-accum mma, then fp32 promote
                    #pragma unroll
                    for (int j = 0; j < 2; ++j)
                        #pragma unroll
                        for (int hh = 0; hh < 2; ++hh) {
                            uint32_t tz[2];
                            mma_f16h(tz, A0k[0], Wk[0][j][2 * hh], Wk[0][j][2 * hh + 1], 0u, 0u);
                            mma_f16h(tz, A0k[1], Wk[1][j][2 * hh], Wk[1][j][2 * hh + 1], tz[0], tz[1]);
                            promote(D0[2 * j + hh], tz[0], tz[1]);
                            mma_f16h(tz, A1k[0], Wk[0][j][2 * hh], Wk[0][j][2 * hh + 1], 0u, 0u);
                            mma_f16h(tz, A1k[1], Wk[1][j][2 * hh], Wk[1][j][2 * hh + 1], tz[0], tz[1]);
                            promote(D1[2 * j + hh], tz[0], tz[1]);
                        }
                }
            }
        }

        // ---- epilogue ----
        float inv00, inv01, inv10, inv11;
        {
            float n00 = 0, n01 = 0, n10 = 0, n11 = 0;
            #pragma unroll
            for (int ky2 = 0; ky2 < 3; ++ky2)
                #pragma unroll
                for (int kx2 = 0; kx2 < 3; ++kx2) {
                    n00 += (sMb[ky2 * 132 + p0 + g + kx2]           == c00) ? 1.0f : 0.0f;
                    n01 += (sMb[ky2 * 132 + p0 + g + 8 + kx2]       == c01) ? 1.0f : 0.0f;
                    n10 += (sMb[(ky2 + 1) * 132 + p0 + g + kx2]     == c10) ? 1.0f : 0.0f;
                    n11 += (sMb[(ky2 + 1) * 132 + p0 + g + 8 + kx2] == c11) ? 1.0f : 0.0f;
                }
            inv00 = 9.0f / n00; inv01 = 9.0f / n01;
            inv10 = 9.0f / n10; inv11 = 9.0f / n11;
        }

        float* Dsm = (float*)(smem + OFF_X + buf * 4 * SLOT_B);   // [64][132] f32
        // pass r = 0
        __syncthreads();   // all LDSM on buf done
        #pragma unroll
        for (int nb = 0; nb < 4; ++nb) {
            const int o0 = h * 32 + nb * 8 + t2;
            const float b0v = sB[o0], b1v = sB[o0 + 1];
            Dsm[o0 * 132 + p0 + g]           = D0[nb][0] * inv00 + b0v;
            Dsm[(o0 + 1) * 132 + p0 + g]     = D0[nb][1] * inv00 + b1v;
            Dsm[o0 * 132 + p0 + g + 8]       = D0[nb][2] * inv01 + b0v;
            Dsm[(o0 + 1) * 132 + p0 + g + 8] = D0[nb][3] * inv01 + b1v;
        }
        __syncthreads();
        {
            const int o = tid >> 3, q = tid & 7;
            const float4* src = (const float4*)(Dsm + o * 132 + q * 16);
            float4* dst = (float4*)(out + (((size_t)b * OCN + o) * HDIM + y0) * WDIM + q * 16);
            #pragma unroll
            for (int j = 0; j < 4; ++j) dst[j] = src[j];
            if (tid < 128)
                out[OUT_MASK_OFF + (b * HDIM + y0) * WDIM + tid] = sMb[1 * 132 + 1 + tid];
        }
        // pass r = 1
        __syncthreads();
        #pragma unroll
        for (int nb = 0; nb < 4; ++nb) {
            const int o0 = h * 32 + nb * 8 + t2;
            const float b0v = sB[o0], b1v = sB[o0 + 1];
            Dsm[o0 * 132 + p0 + g]           = D1[nb][0] * inv10 + b0v;
            Dsm[(o0 + 1) * 132 + p0 + g]     = D1[nb][1] * inv10 + b1v;
            Dsm[o0 * 132 + p0 + g + 8]       = D1[nb][2] * inv11 + b0v;
            Dsm[(o0 + 1) * 132 + p0 + g + 8] = D1[nb][3] * inv11 + b1v;
        }
        __syncthreads();
        {
            const int o = tid >> 3, q = tid & 7;
            const float4* src = (const float4*)(Dsm + o * 132 + q * 16);
            float4* dst = (float4*)(out + (((size_t)b * OCN + o) * HDIM + y0 + 1) * WDIM + q * 16);
            #pragma unroll
            for (int j = 0; j < 4; ++j) dst[j] = src[j];
            if (tid < 128)
                out[OUT_MASK_OFF + (b * HDIM + y0 + 1) * WDIM + tid] = sMb[2 * 132 + 1 + tid];
        }

        // store prefetched mask for next tile
        {
            float* sMn = (float*)(smem + OFF_M + (buf ^ 1) * MASK_BUF);
            #pragma unroll
            for (int j = 0; j < 2; ++j) {
                int i = tid + j * NTHREADS;
                if (i < 528) sMn[i] = mr[j];
            }
        }
        __syncthreads();   // mask + Dsm consumption ordered before next iter

        if (!have_next) break;
        t = tn;
        buf ^= 1;
    }
}

extern "C" void kernel_launch(void* const* d_in, const int* in_sizes, int n_in,
                              void* d_out, int out_size) {
    const float* inp  = (const float*)d_in[0];
    const float* mask = (const float*)d_in[1];
    const float* conv = (const float*)d_in[2];
    const float* bias = (const float*)d_in[3];
    float* out = (float*)d_out;
    (void)in_sizes; (void)n_in; (void)out_size;

    cudaFuncSetAttribute(instconv_mma,
                         cudaFuncAttributeMaxDynamicSharedMemorySize, SMEM_TOTAL);

    prep<<<2048 + 144, 256>>>(inp, conv);
    instconv_mma<<<GRID_MAIN, NTHREADS, SMEM_TOTAL>>>(mask, bias, out);
}

// round 14
// speedup vs baseline: 1.3943x; 1.3943x over previous
#include <cuda_runtime.h>
#include <cuda_fp16.h>
#include <cstdint>

// InstanceConv via warp-level mma.sync f16 GEMM (compute_103-safe).
// Round 14: HMMA rt-ceiling established (~21 cyc/SMSP/mma). Attack makespan:
// 1024 tiles (2 rows x 64 px), 2 CTAs/SM, single-buffered X + cross-CTA
// overlap, direct-STG epilogue, work stealing.
// B=8, C=64, OC=64, H=W=128, K=3, pad=1.

#define BATCH 8
#define CH 64
#define OCN 64
#define HDIM 128
#define WDIM 128
#define NTILES 1024                  // 2-row x 64-px tiles
#define GRID_MAIN 304
#define NTHREADS 256
#define OUT_MASK_OFF (BATCH * OCN * HDIM * WDIM)   // 8388608

// ---- smem layout (bytes, per CTA) ----
#define OFF_W 0
#define W_BYTES (9 * 8192)               // 73728: [tap] 64(c)x64(o) f16, swizzled
#define SLOT_B 8704                      // 68 rows x 128B (x-window + halo)
#define OFF_X (OFF_W + W_BYTES)          // 73728: 4 slots
#define OFF_M (OFF_X + 4 * SLOT_B)       // 108544: mask [4][68] f32 = 1088
#define OFF_B (OFF_M + 1088)             // 109632: bias
#define OFF_CTRL (OFF_B + 256)           // 109888: [0]=next tile; +16 mbar
#define SMEM_TOTAL (OFF_CTRL + 32)       // 109920  (x2 CTAs = 219840 <= 227KB)

__device__ uint32_t g_xt[BATCH * HDIM * WDIM * 32];  // [b][y]: x-major 128B rows, swizzled
__device__ uint4 g_wimg[W_BYTES / 16];
__device__ int g_ctr;

__device__ __forceinline__ uint32_t smem_u32(const void* p) {
    uint32_t a;
    asm("{ .reg .u64 t; cvta.to.shared.u64 t, %1; cvt.u32.u64 %0, t; }" : "=r"(a) : "l"(p));
    return a;
}
__device__ __forceinline__ void ldsm_x4(uint32_t addr, uint32_t* r) {
    asm volatile("ldmatrix.sync.aligned.m8n8.x4.shared.b16 {%0,%1,%2,%3}, [%4];"
                 : "=r"(r[0]), "=r"(r[1]), "=r"(r[2]), "=r"(r[3]) : "r"(addr));
}
__device__ __forceinline__ void ldsm_x4t(uint32_t addr, uint32_t* r) {
    asm volatile("ldmatrix.sync.aligned.m8n8.x4.trans.shared.b16 {%0,%1,%2,%3}, [%4];"
                 : "=r"(r[0]), "=r"(r[1]), "=r"(r[2]), "=r"(r[3]) : "r"(addr));
}
__device__ __forceinline__ void mma_f16(float* d, const uint32_t* a, uint32_t b0, uint32_t b1) {
    asm volatile("mma.sync.aligned.m16n8k16.row.col.f32.f16.f16.f32 "
                 "{%0,%1,%2,%3}, {%4,%5,%6,%7}, {%8,%9}, {%0,%1,%2,%3};"
                 : "+f"(d[0]), "+f"(d[1]), "+f"(d[2]), "+f"(d[3])
                 : "r"(a[0]), "r"(a[1]), "r"(a[2]), "r"(a[3]), "r"(b0), "r"(b1));
}
__device__ __forceinline__ void cpasync16(uint32_t d, const void* s) {
    asm volatile("cp.async.ca.shared.global [%0], [%1], 16;"
                 :: "r"(d), "l"(s) : "memory");
}
#define MBARRIER_INIT(a, n) \
    asm volatile("mbarrier.init.shared.b64 [%0], %1;" :: "r"(a), "r"((uint32_t)(n)) : "memory")
#define MBARRIER_EXPECT_TX(a, tx) \
    asm volatile("mbarrier.arrive.expect_tx.shared.b64 _, [%0], %1;" \
                 :: "r"(a), "r"((uint32_t)(tx)) : "memory")
#define MBARRIER_WAIT_PARITY(a, par) do {                                         \
    uint32_t _m = (a); uint32_t _p = (uint32_t)(par); uint32_t _d;                \
    asm volatile("{\n\t.reg .pred p;\n\t"                                         \
        "mbarrier.try_wait.parity.acquire.cta.shared::cta.b64 p, [%1], %2;\n\t"   \
        "selp.b32 %0, 1, 0, p;\n\t}" : "=r"(_d) : "r"(_m), "r"(_p) : "memory");   \
    if (!_d) {                                                                    \
        asm volatile("{\n\t.reg .pred P1;\n\t"                                    \
            "WL_%=:\n\t"                                                          \
            "mbarrier.try_wait.parity.acquire.cta.shared::cta.b64 P1, [%0], %1, 0x989680;\n\t" \
            "@P1 bra.uni WD_%=;\n\tbra.uni WL_%=;\n\tWD_%=:\n\t}"                 \
            :: "r"(_m), "r"(_p) : "memory");                                      \
    }                                                                             \
} while (0)
#define FENCE_ASYNC() asm volatile("fence.proxy.async.shared::cta;" ::: "memory")
__device__ __forceinline__ void bulk_cp(uint32_t dst, const void* src, uint32_t bytes,
                                        uint32_t mbar) {
    asm volatile("cp.async.bulk.shared::cta.global.mbarrier::complete_tx::bytes "
                 "[%0], [%1], %2, [%3];"
                 :: "r"(dst), "l"(src), "r"(bytes), "r"(mbar) : "memory");
}

// ---------------- prep kernel ----------------
// blocks [0,2048): input -> per (b,y): 128 x-rows of 128B (c-pairs), swizzled
//   with key x&7 so any contiguous x-window lands LDSM-conflict-free.
// blocks [2048,2192): weights -> swizzled [tap][c:64 x 128B] f16 tiles.
__global__ void prep(const float* __restrict__ inp, const float* __restrict__ conv) {
    const int tid = threadIdx.x;
    if (blockIdx.x >= 2048) {
        if (blockIdx.x == 2048 && tid == 0) g_ctr = GRID_MAIN;
        int i = (blockIdx.x - 2048) * 256 + tid;
        if (i < 9 * 64 * 64) {
            int o = i & 63, c = (i >> 6) & 63, tap = i >> 12;
            __half h = __float2half(conv[(o * 64 + c) * 9 + tap]);
            unsigned short* img = (unsigned short*)g_wimg;
            uint32_t byte = (uint32_t)(c * 128 + ((((o >> 3) ^ (c & 7))) << 4) + (o & 7) * 2);
            img[(tap * 8192 + byte) >> 1] = __half_as_ushort(h);
        }
        return;
    }
    __shared__ float tile[64][65];
    const int blk = blockIdx.x;
    const int half = blk & 1, y = (blk >> 1) & 127, b = blk >> 8;
    const int x0 = half * 64;
    #pragma unroll
    for (int i = 0; i < 16; ++i) {
        int idx = i * 256 + tid;
        int c = idx >> 6, x = idx & 63;
        tile[c][x] = inp[((b * CH + c) * HDIM + y) * WDIM + x0 + x];
    }
    __syncthreads();
    #pragma unroll
    for (int i = 0; i < 8; ++i) {
        int idx = i * 256 + tid;
        int x = (idx >> 5) + x0, cw = idx & 31;
        __half h0 = __float2half(tile[2 * (idx & 31)][idx >> 5]);
        __half h1 = __float2half(tile[2 * (idx & 31) + 1][idx >> 5]);
        uint32_t v = (uint32_t)__half_as_ushort(h0) | ((uint32_t)__half_as_ushort(h1) << 16);
        int u = cw >> 2;
        int dst = ((b * HDIM + y) << 12) + (x << 5)
                + (((u ^ (x & 7))) << 2) + (cw & 3);
        g_xt[dst] = v;
    }
}

// ---------------- main persistent kernel ----------------
__global__ __launch_bounds__(NTHREADS, 2)
void instconv_mma(const float* __restrict__ mask,
                  const float* __restrict__ bias,
                  float* __restrict__ out) {
    extern __shared__ char smem[];
    const uint32_t sb = smem_u32(smem);
    const int tid = threadIdx.x;
    const int wid = tid >> 5;
    const int lane = tid & 31;
    const int g = lane >> 2;
    const int t2 = (lane & 3) * 2;
    const int h = wid >> 2;           // oc half (0: oc<32, 1: oc>=32)
    const int p0 = (wid & 3) * 16;    // 16-px group within 64-px tile
    const int lane15 = lane & 15;
    const int laneHi = lane >> 4;

    volatile int* sCtrl = (volatile int*)(smem + OFF_CTRL);
    const uint32_t mbar = sb + OFF_CTRL + 16;

    // stage weights once (cp.async group)
    {
        const uint4* src = g_wimg;
        #pragma unroll 4
        for (int i = tid; i < W_BYTES / 16; i += NTHREADS)
            cpasync16(sb + OFF_W + i * 16, src + i);
        asm volatile("cp.async.commit_group;" ::: "memory");
    }
    if (tid < 64) ((float*)(smem + OFF_B))[tid] = bias[tid];
    if (tid == 0) MBARRIER_INIT(mbar, 1);
    const float* sB = (const float*)(smem + OFF_B);
    float* sM = (float*)(smem + OFF_M);

    const uint32_t wLane = sb + OFF_W + (uint32_t)(lane15 * 128);
    uint32_t wcs[2];
    #pragma unroll
    for (int j = 0; j < 2; ++j)
        wcs[j] = (uint32_t)(((((2 * h + j) * 2 + laneHi) ^ (lane & 7))) << 4);

    // ---- prologue: stage first tile ----
    int t = blockIdx.x;
    {
        const int b = t >> 7, rem = t & 127;
        const int y0 = (rem >> 1) * 2, x0 = (rem & 1) * 64;
        if (tid == 0) {
            FENCE_ASYNC();
            const int srow = (x0 == 0) ? 0 : 63;
            const uint32_t doff = (x0 == 0) ? 128u : 0u;
            const uint32_t nbytes = (x0 == 0) ? 66 * 128 : 65 * 128;
            MBARRIER_EXPECT_TX(mbar, 4 * nbytes);
            #pragma unroll
            for (int s = 0; s < 4; ++s) {
                int ys = y0 - 1 + s; ys = ys < 0 ? 0 : (ys > 127 ? 127 : ys);
                bulk_cp(sb + OFF_X + s * SLOT_B + doff,
                        (const char*)g_xt + (((size_t)(b * HDIM + ys)) << 14) + srow * 128,
                        nbytes, mbar);
            }
        }
        for (int i = tid; i < 272; i += NTHREADS) {
            int r = i / 68, xi = i - r * 68;
            int ys = y0 + r - 1, xs = x0 + xi - 1;
            float v = -1.0f;
            if ((unsigned)ys < (unsigned)HDIM && (unsigned)xs < (unsigned)WDIM && xi < 66)
                v = mask[(b * HDIM + ys) * WDIM + xs];
            sM[i] = v;
        }
        if (tid == 0) sCtrl[0] = atomicAdd(&g_ctr, 1);
    }
    asm volatile("cp.async.wait_group 0;" ::: "memory");
    __syncthreads();   // W + mask + sCtrl visible

    int ph = 0;

    for (;;) {
        const int b = t >> 7, rem = t & 127;
        const int y0 = (rem >> 1) * 2, x0 = (rem & 1) * 64;

        MBARRIER_WAIT_PARITY(mbar, ph); ph ^= 1;
        const int tn = sCtrl[0];
        const bool have_next = tn < NTILES;
        __syncthreads();   // everyone has tn before thread0 overwrites sCtrl
        if (tid == 0) sCtrl[0] = atomicAdd(&g_ctr, 1);

        const float c00 = sM[1 * 68 + 1 + p0 + g];
        const float c01 = sM[1 * 68 + 1 + p0 + g + 8];
        const float c10 = sM[2 * 68 + 1 + p0 + g];
        const float c11 = sM[2 * 68 + 1 + p0 + g + 8];

        float D0[4][4], D1[4][4];
        #pragma unroll
        for (int nb = 0; nb < 4; ++nb)
            #pragma unroll
            for (int j = 0; j < 4; ++j) { D0[nb][j] = 0.0f; D1[nb][j] = 0.0f; }

        #pragma unroll
        for (int ky = 0; ky < 3; ++ky) {
            const uint32_t baseA0 = sb + OFF_X + (uint32_t)(ky * SLOT_B);
            const uint32_t baseA1 = baseA0 + SLOT_B;
            const float* mT0 = sM + ky * 68;
            const float* mT1 = sM + (ky + 1) * 68;

            #pragma unroll 1
            for (int kx = 0; kx < 3; ++kx) {
                const uint32_t mk00 = (mT0[p0 + g + kx]     == c00) ? 0xFFFFFFFFu : 0u;
                const uint32_t mk01 = (mT0[p0 + g + 8 + kx] == c01) ? 0xFFFFFFFFu : 0u;
                const uint32_t mk10 = (mT1[p0 + g + kx]     == c10) ? 0xFFFFFFFFu : 0u;
                const uint32_t mk11 = (mT1[p0 + g + 8 + kx] == c11) ? 0xFFFFFFFFu : 0u;

                const uint32_t rowb = (uint32_t)((p0 + lane15 + kx) * 128);
                const int xorm = (lane15 + kx + 7) & 7;
                const uint32_t wTap = wLane + (uint32_t)((ky * 3 + kx) * 8192);

                #pragma unroll
                for (int k = 0; k < 4; ++k) {
                    const uint32_t colA = (uint32_t)(((k * 2 + laneHi) ^ xorm) << 4);
                    uint32_t a0[4], a1[4];
                    ldsm_x4(baseA0 + rowb + colA, a0);
                    ldsm_x4(baseA1 + rowb + colA, a1);
                    a0[0] &= mk00; a0[2] &= mk00; a0[1] &= mk01; a0[3] &= mk01;
                    a1[0] &= mk10; a1[2] &= mk10; a1[1] &= mk11; a1[3] &= mk11;

                    const uint32_t wk = wTap + (uint32_t)(k * 2048);
                    uint32_t w0[4], w1[4];
                    ldsm_x4t(wk + wcs[0], w0);
                    ldsm_x4t(wk + wcs[1], w1);
                    mma_f16(D0[0], a0, w0[0], w0[1]);
                    mma_f16(D1[0], a1, w0[0], w0[1]);
                    mma_f16(D0[1], a0, w0[2], w0[3]);
                    mma_f16(D1[1], a1, w0[2], w0[3]);
                    mma_f16(D0[2], a0, w1[0], w1[1]);
                    mma_f16(D1[2], a1, w1[0], w1[1]);
                    mma_f16(D0[3], a0, w1[2], w1[3]);
                    mma_f16(D1[3], a1, w1[2], w1[3]);
                }
            }
        }
        __syncthreads();   // all X/sM-compute reads done

        // stage NEXT tile into X now (overlaps epilogue + other CTA's compute)
        const int bn = tn >> 7, remn = tn & 127;
        const int yn0 = (remn >> 1) * 2, xn0 = (remn & 1) * 64;
        if (tid == 0 && have_next) {
            FENCE_ASYNC();
            const int srow = (xn0 == 0) ? 0 : 63;
            const uint32_t doff = (xn0 == 0) ? 128u : 0u;
            const uint32_t nbytes = (xn0 == 0) ? 66 * 128 : 65 * 128;
            MBARRIER_EXPECT_TX(mbar, 4 * nbytes);
            #pragma unroll
            for (int s = 0; s < 4; ++s) {
                int ys = yn0 - 1 + s; ys = ys < 0 ? 0 : (ys > 127 ? 127 : ys);
                bulk_cp(sb + OFF_X + s * SLOT_B + doff,
                        (const char*)g_xt + (((size_t)(bn * HDIM + ys)) << 14) + srow * 128,
                        nbytes, mbar);
            }
        }

        // prefetch next-tile mask into registers (hidden by epilogue)
        float mr0 = -1.0f, mr1 = -1.0f;
        if (have_next) {
            {
                int r = tid / 68, xi = tid - r * 68;
                int ys = yn0 + r - 1, xs = xn0 + xi - 1;
                if ((unsigned)ys < (unsigned)HDIM && (unsigned)xs < (unsigned)WDIM && xi < 66)
                    mr0 = mask[(bn * HDIM + ys) * WDIM + xs];
            }
            int i1 = tid + NTHREADS;
            if (i1 < 272) {
                int r = i1 / 68, xi = i1 - r * 68;
                int ys = yn0 + r - 1, xs = xn0 + xi - 1;
                if ((unsigned)ys < (unsigned)HDIM && (unsigned)xs < (unsigned)WDIM && xi < 66)
                    mr1 = mask[(bn * HDIM + ys) * WDIM + xs];
            }
        }

        // inv factors (reads sM)
        float inv00, inv01, inv10, inv11;
        {
            float n00 = 0, n01 = 0, n10 = 0, n11 = 0;
            #pragma unroll
            for (int ky2 = 0; ky2 < 3; ++ky2)
                #pragma unroll
                for (int kx2 = 0; kx2 < 3; ++kx2) {
                    n00 += (sM[ky2 * 68 + p0 + g + kx2]           == c00) ? 1.0f : 0.0f;
                    n01 += (sM[ky2 * 68 + p0 + g + 8 + kx2]       == c01) ? 1.0f : 0.0f;
                    n10 += (sM[(ky2 + 1) * 68 + p0 + g + kx2]     == c10) ? 1.0f : 0.0f;
                    n11 += (sM[(ky2 + 1) * 68 + p0 + g + 8 + kx2] == c11) ? 1.0f : 0.0f;
                }
            inv00 = 9.0f / n00; inv01 = 9.0f / n01;
            inv10 = 9.0f / n10; inv11 = 9.0f / n11;
        }

        // direct-STG epilogue from registers
        #pragma unroll
        for (int q = 0; q < 4; ++q) {
            const int o0 = h * 32 + q * 8 + t2;
            const float b0v = sB[o0], b1v = sB[o0 + 1];
            float* r0a = out + (((size_t)b * OCN + o0) * HDIM + y0) * WDIM + x0;
            float* r0b = r0a + (size_t)HDIM * WDIM;   // o0+1
            float* r1a = r0a + WDIM;                  // row y0+1
            float* r1b = r0b + WDIM;
            const int pA = p0 + g, pB = p0 + g + 8;
            r0a[pA] = D0[q][0] * inv00 + b0v;
            r0b[pA] = D0[q][1] * inv00 + b1v;
            r0a[pB] = D0[q][2] * inv01 + b0v;
            r0b[pB] = D0[q][3] * inv01 + b1v;
            r1a[pA] = D1[q][0] * inv10 + b0v;
            r1b[pA] = D1[q][1] * inv10 + b1v;
            r1a[pB] = D1[q][2] * inv11 + b0v;
            r1b[pB] = D1[q][3] * inv11 + b1v;
        }
        // mask passthrough: 2 rows x 64 px
        if (tid < 128) {
            const int r = tid >> 6, px = tid & 63;
            out[OUT_MASK_OFF + (b * HDIM + y0 + r) * WDIM + x0 + px] =
                sM[(r + 1) * 68 + 1 + px];
        }
        __syncthreads();   // all sM reads done before overwrite

        // store prefetched mask for next tile
        sM[tid] = mr0;
        if (tid + NTHREADS < 272) sM[tid + NTHREADS] = mr1;
        __syncthreads();   // sM writes visible before next compute

        if (!have_next) break;
        t = tn;
    }
}

extern "C" void kernel_launch(void* const* d_in, const int* in_sizes, int n_in,
                              void* d_out, int out_size) {
    const float* inp  = (const float*)d_in[0];
    const float* mask = (const float*)d_in[1];
    const float* conv = (const float*)d_in[2];
    const float* bias = (const float*)d_in[3];
    float* out = (float*)d_out;
    (void)in_sizes; (void)n_in; (void)out_size;

    cudaFuncSetAttribute(instconv_mma,
                         cudaFuncAttributeMaxDynamicSharedMemorySize, SMEM_TOTAL);

    prep<<<2048 + 144, 256>>>(inp, conv);
    instconv_mma<<<GRID_MAIN, NTHREADS, SMEM_TOTAL>>>(mask, bias, out);
}